// round 17
// baseline (speedup 1.0000x reference)
#include <cuda_runtime.h>
#include <cstdint>

#define XS    128
#define BATCH 8
#define MPTS  500000
#define NUNIT (BATCH * XS * 8)               // 8192 (plane, strip) zero units
#define GRID_ELEMS (BATCH * XS * XS * XS)    // 64 MiB

// Scratch (device globals: zero-initialized at load; g_done self-resets)
__device__ float g_grid[GRID_ELEMS];
__device__ int   g_done[NUNIT];

// ---- L2 evict-last cache-policy helpers ----
__device__ __forceinline__ uint64_t mk_evict_last() {
    uint64_t pol;
    asm("createpolicy.fractional.L2::evict_last.b64 %0, 1.0;" : "=l"(pol));
    return pol;
}
__device__ __forceinline__ void red_add_el(float* p, float v, uint64_t pol) {
    asm volatile("red.global.L2::cache_hint.add.f32 [%0], %1, %2;"
                 :: "l"(p), "f"(v), "l"(pol) : "memory");
}
__device__ __forceinline__ float4 ldg4_el(const float4* p, uint64_t pol) {
    float4 r;
    asm volatile("ld.global.L2::cache_hint.v4.f32 {%0,%1,%2,%3}, [%4], %5;"
                 : "=f"(r.x), "=f"(r.y), "=f"(r.z), "=f"(r.w)
                 : "l"(p), "l"(pol) : "memory");
    return r;
}
__device__ __forceinline__ void stg4_el(float4* p, float4 v, uint64_t pol) {
    asm volatile("st.global.L2::cache_hint.v4.f32 [%0], {%1,%2,%3,%4}, %5;"
                 :: "l"(p), "f"(v.x), "f"(v.y), "f"(v.z), "f"(v.w), "l"(pol)
                 : "memory");
}

// ---------------------------------------------------------------------------
// Kernel 1: scatter-add, 4 points/thread (1M threads) for 100% occupancy:
// 3x int4 + 1x float4 streaming loads, 4 evict-last REDs, ~32 regs.
// Block 0 zeroes the 16 output accumulators.
// ---------------------------------------------------------------------------
__global__ void __launch_bounds__(256, 8) scatter_kernel(
        const int4*   __restrict__ idx4,
        const float4* __restrict__ val4,
        float*        __restrict__ d_out) {
    if (blockIdx.x == 0 && threadIdx.x < 2 * BATCH) d_out[threadIdx.x] = 0.f;

    const int nquads = (BATCH * MPTS) / 4;          // 1,000,000
    int tid = blockIdx.x * blockDim.x + threadIdx.x;
    if (tid >= nquads) return;

    const uint64_t pol = mk_evict_last();

    int b = tid / (MPTS / 4);                       // 4 pts/thread, same batch
    unsigned base = (unsigned)b << 21;

    int4 a0 = __ldcs(&idx4[3 * tid + 0]);           // i0 j0 k0 i1
    int4 a1 = __ldcs(&idx4[3 * tid + 1]);           // j1 k1 i2 j2
    int4 a2 = __ldcs(&idx4[3 * tid + 2]);           // k2 i3 j3 k3
    float4 v = __ldcs(&val4[tid]);

    red_add_el(&g_grid[base + ((unsigned)a0.x << 14) + ((unsigned)a0.y << 7) + (unsigned)a0.z], v.x, pol);
    red_add_el(&g_grid[base + ((unsigned)a0.w << 14) + ((unsigned)a1.x << 7) + (unsigned)a1.y], v.y, pol);
    red_add_el(&g_grid[base + ((unsigned)a1.z << 14) + ((unsigned)a1.w << 7) + (unsigned)a2.x], v.z, pol);
    red_add_el(&g_grid[base + ((unsigned)a2.y << 14) + ((unsigned)a2.z << 7) + (unsigned)a2.w], v.w, pol);
}

// ---------------------------------------------------------------------------
__device__ __forceinline__ void diff4(const float4& a, const float4& b,
                                      float& tv, float& mse) {
    float d0 = b.x - a.x, d1 = b.y - a.y, d2 = b.z - a.z, d3 = b.w - a.w;
    tv  += fabsf(d0) + fabsf(d1) + fabsf(d2) + fabsf(d3);
    mse += d0 * d0 + d1 * d1 + d2 * d2 + d3 * d3;
}
__device__ __forceinline__ void kdiffs(const float4& c, bool cross,
                                       float& tv, float& mse) {
    float d0 = c.y - c.x, d1 = c.z - c.y, d2 = c.w - c.z;
    tv  += fabsf(d0) + fabsf(d1) + fabsf(d2);
    mse += d0 * d0 + d1 * d1 + d2 * d2;
    float nx = __shfl_down_sync(0xffffffffu, c.x, 1);
    if (cross) { float d3 = nx - c.w; tv += fabsf(d3); mse += d3 * d3; }
}
// zero one (plane, strip) unit: 16 rows x 32 float4 = 512 float4
__device__ __forceinline__ void zero_unit(int p, int s, int tid, uint64_t pol) {
    float4* gw = (float4*)g_grid;
    const long ub = (long)p * 4096 + s * 512;
    const float4 z = make_float4(0.f, 0.f, 0.f, 0.f);
    stg4_el(&gw[ub + tid], z, pol);
    stg4_el(&gw[ub + 256 + tid], z, pol);
    if (tid == 0) g_done[p * 8 + s] = 0;
}

// ---------------------------------------------------------------------------
// Kernel 2: TV+MSE reduce + re-zero (R16 form) with occupancy raised to
// 6 blocks/SM via __launch_bounds__(256, 6) — live data is only ~20 regs.
// Block = (batch, 4-plane chunk, 16-row j-strip) -> 2048 blocks.
// ---------------------------------------------------------------------------
__global__ void __launch_bounds__(256, 6) reduce_zero_kernel(float* __restrict__ d_out) {
    const int rb    = blockIdx.x;                  // 0..2047
    const int b     = rb >> 8;
    const int local = rb & 255;
    const int ic    = local >> 3;                  // i-chunk 0..31
    const int s     = local & 7;                   // j-strip 0..7 (16 rows)
    const int p0    = b * XS + ic * 4;             // first owned plane
    const int lane  = threadIdx.x & 31;
    const int jg    = threadIdx.x >> 5;            // jgroup 0..7 (2 rows)
    const int jrow0 = s * 16 + jg * 2;
    const bool has_jb = !(s == 7 && jg == 7);      // row jrow0+2 exists?
    const bool crossk = (lane != 31);
    const float4* __restrict__ g4 = (const float4*)g_grid;

    const uint64_t pol = mk_evict_last();
    const long pb = (long)p0 << 12;
    const int  fo = jrow0 * 32 + lane;
    const float4 z = make_float4(0.f, 0.f, 0.f, 0.f);

    float tv = 0.f, mse = 0.f;
    float4 c0, c1, jb;

    // plane p0
    c0 = ldg4_el(&g4[pb + fo], pol);
    c1 = ldg4_el(&g4[pb + fo + 32], pol);
    jb = has_jb ? ldg4_el(&g4[pb + fo + 64], pol) : z;
    kdiffs(c0, crossk, tv, mse);
    kdiffs(c1, crossk, tv, mse);
    diff4(c0, c1, tv, mse);
    if (has_jb) diff4(c1, jb, tv, mse);

    // planes p0+1..p0+3: i-diffs via register carry, then own k/j
    #pragma unroll
    for (int t = 1; t < 4; ++t) {
        const long pbt = pb + (long)t * 4096;
        float4 n0 = ldg4_el(&g4[pbt + fo], pol);
        float4 n1 = ldg4_el(&g4[pbt + fo + 32], pol);
        jb = has_jb ? ldg4_el(&g4[pbt + fo + 64], pol) : z;
        diff4(c0, n0, tv, mse);
        diff4(c1, n1, tv, mse);
        kdiffs(n0, crossk, tv, mse);
        kdiffs(n1, crossk, tv, mse);
        diff4(n0, n1, tv, mse);
        if (has_jb) diff4(n1, jb, tv, mse);
        c0 = n0; c1 = n1;
    }
    // seam plane p0+4 (i-diffs only)
    if (ic < 31) {
        const long pbs = pb + 4L * 4096;
        float4 e0 = ldg4_el(&g4[pbs + fo], pol);
        float4 e1 = ldg4_el(&g4[pbs + fo + 32], pol);
        diff4(c0, e0, tv, mse);
        diff4(c1, e1, tv, mse);
    }

    // block reduce -> 2 atomics into d_out
    #pragma unroll
    for (int off = 16; off > 0; off >>= 1) {
        tv  += __shfl_down_sync(0xffffffffu, tv,  off);
        mse += __shfl_down_sync(0xffffffffu, mse, off);
    }
    __shared__ float stv[8], smse[8];
    if (lane == 0) { stv[jg] = tv; smse[jg] = mse; }
    __syncthreads();
    if (threadIdx.x == 0) {
        float ttv = 0.f, tmse = 0.f;
        #pragma unroll
        for (int w = 0; w < 8; w++) { ttv += stv[w]; tmse += smse[w]; }
        const float tv_norm  = 1.f / (float)(XS * XS * XS);
        const float mse_norm = 1.f / (float)(2 * XS * XS - 2 * XS);
        atomicAdd(&d_out[b],         ttv  * tv_norm);
        atomicAdd(&d_out[BATCH + b], tmse * mse_norm);
    }

    // ---- (plane, strip)-granular zero protocol (R16 form, verified) ----
    __shared__ int zmask;
    if (threadIdx.x == 0) zmask = 0;
    __syncthreads();                                // all grid reads retired
    if (threadIdx.x == 0) {
        __threadfence();
        int m = 0;
        #pragma unroll
        for (int t = 0; t < 4; ++t) {               // own units
            int tgt = 1 + (s > 0 ? 1 : 0) + ((t == 0 && ic > 0) ? 1 : 0);
            if (atomicAdd(&g_done[(p0 + t) * 8 + s], 1) + 1 == tgt)
                m |= 1 << t;
        }
        if (s < 7) {                                // j-next units we read
            #pragma unroll
            for (int t = 0; t < 4; ++t) {
                int tgt = 2 + ((t == 0 && ic > 0) ? 1 : 0);
                if (atomicAdd(&g_done[(p0 + t) * 8 + s + 1], 1) + 1 == tgt)
                    m |= 1 << (4 + t);
            }
        }
        if (ic < 31) {                              // seam unit we read
            int tgt = 2 + (s > 0 ? 1 : 0);
            if (atomicAdd(&g_done[(p0 + 4) * 8 + s], 1) + 1 == tgt)
                m |= 1 << 8;
        }
        zmask = m;
    }
    __syncthreads();
    int m = zmask;
    #pragma unroll
    for (int t = 0; t < 4; ++t)
        if (m & (1 << t))       zero_unit(p0 + t, s,     threadIdx.x, pol);
    #pragma unroll
    for (int t = 0; t < 4; ++t)
        if (m & (1 << (4 + t))) zero_unit(p0 + t, s + 1, threadIdx.x, pol);
    if (m & (1 << 8))           zero_unit(p0 + 4, s,     threadIdx.x, pol);
}

// ---------------------------------------------------------------------------
extern "C" void kernel_launch(void* const* d_in, const int* in_sizes, int n_in,
                              void* d_out, int out_size) {
    const int*   indices = (const int*)d_in[0];    // (B, M, 3) int32
    const float* values  = (const float*)d_in[1];  // (B, M) float32
    float* out = (float*)d_out;                    // (2, B) float32

    {
        int nquads = (BATCH * MPTS) / 4;            // 1,000,000
        int threads = 256;
        int blocks = (nquads + threads - 1) / threads;
        scatter_kernel<<<blocks, threads>>>((const int4*)indices,
                                            (const float4*)values, out);
    }
    {
        reduce_zero_kernel<<<2048, 256>>>(out);
    }
}